// round 1
// baseline (speedup 1.0000x reference)
#include <cuda_runtime.h>

// Problem constants
#define NN    25000
#define NPAD  25008          // multiple of 16
#define EE    400000
#define FN    32
#define FE    16
#define HH    16
#define MM    16
#define MPITERS 3

// ---------------- scratch (device globals; no allocation allowed) ----------
__device__ float g_hidden [NPAD * HH];
__device__ float g_hidden0[NPAD * HH];
__device__ float g_T      [NPAD * FE * MM];   // T[n][f*16+m] = sum_h W_edge[f,m,h]*hidden[n,h]
__device__ float g_bb     [NPAD * MM];        // bb[n][m]    = sum_h b_edge[m,h]*hidden[n,h]
__device__ float g_msg    [NPAD * MM];        // aggregated messages

// ---------------- f32x2 helpers (Blackwell packed fp32 pipe) ---------------
__device__ __forceinline__ unsigned long long pk2(float lo, float hi) {
    unsigned long long d;
    asm("mov.b64 %0, {%1, %2};" : "=l"(d) : "r"(__float_as_uint(lo)), "r"(__float_as_uint(hi)));
    return d;
}
__device__ __forceinline__ unsigned long long fma2(unsigned long long a,
                                                   unsigned long long b,
                                                   unsigned long long c) {
    unsigned long long d;
    asm("fma.rn.f32x2 %0, %1, %2, %3;" : "=l"(d) : "l"(a), "l"(b), "l"(c));
    return d;
}
__device__ __forceinline__ float upk_sum(unsigned long long v) {
    unsigned int a, b;
    asm("mov.b64 {%0, %1}, %2;" : "=r"(a), "=r"(b) : "l"(v));
    return __uint_as_float(a) + __uint_as_float(b);
}

__device__ __forceinline__ float dot4(float4 a, float4 b) {
    float r = a.x * b.x;
    r = fmaf(a.y, b.y, r);
    r = fmaf(a.z, b.z, r);
    r = fmaf(a.w, b.w, r);
    return r;
}

// ---------------- kernel 1: hidden0 = NF @ W_init + b_init -----------------
__global__ __launch_bounds__(256)
void init_kernel(const float* __restrict__ nf, const float* __restrict__ Wi,
                 const float* __restrict__ bi) {
    __shared__ float Wsh[FN * HH];   // [f*16+j]
    int tid = threadIdx.x;
    int j  = tid & 15;
    int nl = tid >> 4;
    int n  = blockIdx.x * 16 + nl;
    for (int idx = tid; idx < FN * HH; idx += 256) Wsh[idx] = Wi[idx];
    __syncthreads();
    int nr = (n < NN) ? n : (NN - 1);              // clamp reads for padding nodes
    const float* row = nf + (long)nr * FN;
    float acc = bi[j];
#pragma unroll
    for (int f = 0; f < FN; f++) acc = fmaf(row[f], Wsh[f * 16 + j], acc);
    g_hidden [n * 16 + j] = acc;
    g_hidden0[n * 16 + j] = acc;
}

// ---------------- kernel 2: per-node T and bb ------------------------------
// thread = (f, m); W column register-resident; loop over 64 nodes/block.
__global__ __launch_bounds__(256)
void t_kernel(const float* __restrict__ We, const float* __restrict__ be) {
    __shared__ __align__(16) float sh[64 * HH];
    int tid = threadIdx.x;
    int f = tid >> 4;
    int m = tid & 15;

    const float4* wp = (const float4*)(We + (f * 256 + m * 16));
    float4 w0 = wp[0], w1 = wp[1], w2 = wp[2], w3 = wp[3];

    float4 b0 = make_float4(0, 0, 0, 0), b1 = b0, b2 = b0, b3 = b0;
    if (f == 0) {
        const float4* bp = (const float4*)(be + m * 16);
        b0 = bp[0]; b1 = bp[1]; b2 = bp[2]; b3 = bp[3];
    }

    int base = blockIdx.x * 64;
    int cnt = NN - base;
    if (cnt > 64) cnt = 64;

    for (int idx = tid; idx < cnt * HH; idx += 256)
        sh[idx] = g_hidden[base * HH + idx];
    __syncthreads();

#pragma unroll 2
    for (int nl = 0; nl < cnt; nl++) {
        const float4* hp = (const float4*)(sh + nl * HH);
        float4 h0 = hp[0], h1 = hp[1], h2 = hp[2], h3 = hp[3];
        float acc = dot4(w0, h0) + dot4(w1, h1) + dot4(w2, h2) + dot4(w3, h3);
        g_T[(long)(base + nl) * 256 + tid] = acc;
        if (f == 0) {
            float bacc = dot4(b0, h0) + dot4(b1, h1) + dot4(b2, h2) + dot4(b3, h3);
            g_bb[(base + nl) * 16 + m] = bacc;
        }
    }
}

// ---------------- zero messages -------------------------------------------
__global__ __launch_bounds__(256)
void zero_msg_kernel() {
    int i = blockIdx.x * 256 + threadIdx.x;
    if (i < NPAD * MM) g_msg[i] = 0.f;
}

// ---------------- kernel 3: per-edge message + scatter ---------------------
// thread = (edge, m). msg[e,m] = sum_f ef[e,f]*T[s][f*16+m] + bb[s,m]
__global__ __launch_bounds__(256)
void edge_kernel(const float* __restrict__ ef, const int* __restrict__ recv,
                 const int* __restrict__ send) {
    int tid = threadIdx.x;
    int m = tid & 15;
    int e = blockIdx.x * 16 + (tid >> 4);

    int s = send[e];
    const float4* ep = (const float4*)(ef + (long)e * FE);
    float4 a0 = ep[0], a1 = ep[1], a2 = ep[2], a3 = ep[3];

    const float* Tr = g_T + (long)s * 256 + m;
    float acc = g_bb[s * 16 + m];
    acc = fmaf(a0.x, Tr[0 * 16], acc);
    acc = fmaf(a0.y, Tr[1 * 16], acc);
    acc = fmaf(a0.z, Tr[2 * 16], acc);
    acc = fmaf(a0.w, Tr[3 * 16], acc);
    acc = fmaf(a1.x, Tr[4 * 16], acc);
    acc = fmaf(a1.y, Tr[5 * 16], acc);
    acc = fmaf(a1.z, Tr[6 * 16], acc);
    acc = fmaf(a1.w, Tr[7 * 16], acc);
    acc = fmaf(a2.x, Tr[8 * 16], acc);
    acc = fmaf(a2.y, Tr[9 * 16], acc);
    acc = fmaf(a2.z, Tr[10 * 16], acc);
    acc = fmaf(a2.w, Tr[11 * 16], acc);
    acc = fmaf(a3.x, Tr[12 * 16], acc);
    acc = fmaf(a3.y, Tr[13 * 16], acc);
    acc = fmaf(a3.z, Tr[14 * 16], acc);
    acc = fmaf(a3.w, Tr[15 * 16], acc);

    atomicAdd(&g_msg[recv[e] * 16 + m], acc);
}

// ---------------- kernel 4: GRU over 32-step scalar sequence ---------------
// 16 threads per node (thread j owns hidden unit j). Wh columns register-
// resident as f32x2 pairs over the contraction index. h exchanged through
// double-buffered shared memory; 1 __syncwarp per step.
__global__ __launch_bounds__(256)
void gru_kernel(const float* __restrict__ Wi, const float* __restrict__ Wh,
                const float* __restrict__ bi, const float* __restrict__ bh) {
    __shared__ __align__(16) float sh_h[2][16][16];
    __shared__ float sh_seq[16][32];

    int tid = threadIdx.x;
    int j  = tid & 15;
    int nl = tid >> 4;
    int n  = blockIdx.x * 16 + nl;

    // pack Wh columns: pair over rows (i, i+1)
    unsigned long long wz[8], wr[8], wh[8];
#pragma unroll
    for (int k = 0; k < 8; k++) {
        wz[k] = pk2(Wh[(2 * k) * 48 + j],      Wh[(2 * k + 1) * 48 + j]);
        wr[k] = pk2(Wh[(2 * k) * 48 + 16 + j], Wh[(2 * k + 1) * 48 + 16 + j]);
        wh[k] = pk2(Wh[(2 * k) * 48 + 32 + j], Wh[(2 * k + 1) * 48 + 32 + j]);
    }
    float wiz = Wi[j], wir = Wi[16 + j], wih = Wi[32 + j];
    float biz = bi[j], bir = bi[16 + j], bih = bi[32 + j];
    float bhz = bh[j], bhr = bh[16 + j], bhh = bh[32 + j];

    sh_seq[nl][j]      = g_hidden[n * 16 + j];
    sh_seq[nl][16 + j] = g_msg   [n * 16 + j];
    sh_h[0][nl][j] = 0.f;
    float hj = 0.f;
    __syncthreads();

#pragma unroll 1
    for (int t = 0; t < 32; t++) {
        int cur = t & 1;
        float x = sh_seq[nl][t];
        const ulonglong2* hp = (const ulonglong2*)sh_h[cur][nl];
        unsigned long long az = pk2(bhz, 0.f);
        unsigned long long ar = pk2(bhr, 0.f);
        unsigned long long ah = pk2(bhh, 0.f);
#pragma unroll
        for (int k = 0; k < 4; k++) {
            ulonglong2 p = hp[k];
            az = fma2(p.x, wz[2 * k],     az);
            az = fma2(p.y, wz[2 * k + 1], az);
            ar = fma2(p.x, wr[2 * k],     ar);
            ar = fma2(p.y, wr[2 * k + 1], ar);
            ah = fma2(p.x, wh[2 * k],     ah);
            ah = fma2(p.y, wh[2 * k + 1], ah);
        }
        float ghz = upk_sum(az);
        float ghr = upk_sum(ar);
        float ghh = upk_sum(ah);

        float gz = fmaf(x, wiz, biz) + ghz;
        float gr = fmaf(x, wir, bir) + ghr;
        float z = 1.f / (1.f + __expf(-gz));
        float r = 1.f / (1.f + __expf(-gr));
        float ga = fmaf(x, wih, bih) + r * ghh;
        float hc = 2.f / (1.f + __expf(-2.f * ga)) - 1.f;   // tanh(ga)
        hj = hc + z * (hj - hc);                            // z*h + (1-z)*hc

        sh_h[cur ^ 1][nl][j] = hj;
        __syncwarp();
    }
    g_hidden[n * 16 + j] = hj;
}

// ---------------- readout --------------------------------------------------
__global__ void zero_out_kernel(float* out) { out[0] = 0.f; }

__global__ __launch_bounds__(256)
void readout_kernel(const float* __restrict__ Wri, const float* __restrict__ bri,
                    const float* __restrict__ Wrj, const float* __restrict__ brj,
                    float* __restrict__ out) {
    int n = blockIdx.x * 256 + threadIdx.x;
    float p = 0.f;
    if (n < NN) {
        const float4* hp  = (const float4*)(g_hidden  + n * 16);
        const float4* h0p = (const float4*)(g_hidden0 + n * 16);
        const float4* wi  = (const float4*)Wri;
        const float4* wj  = (const float4*)Wrj;
        float4 h0 = hp[0], h1 = hp[1], h2 = hp[2], h3 = hp[3];
        float4 g0 = h0p[0], g1 = h0p[1], g2 = h0p[2], g3 = h0p[3];
        float iv = bri[0]
                 + dot4(h0, wi[0]) + dot4(h1, wi[1]) + dot4(h2, wi[2]) + dot4(h3, wi[3])
                 + dot4(g0, wi[4]) + dot4(g1, wi[5]) + dot4(g2, wi[6]) + dot4(g3, wi[7]);
        float jv = brj[0]
                 + dot4(h0, wj[0]) + dot4(h1, wj[1]) + dot4(h2, wj[2]) + dot4(h3, wj[3]);
        p = iv * jv;
    }
#pragma unroll
    for (int off = 16; off > 0; off >>= 1)
        p += __shfl_down_sync(0xffffffffu, p, off);
    if ((threadIdx.x & 31) == 0) atomicAdd(out, p);
}

// ---------------- launch ---------------------------------------------------
extern "C" void kernel_launch(void* const* d_in, const int* in_sizes, int n_in,
                              void* d_out, int out_size) {
    const float* nf     = (const float*)d_in[0];
    const float* ef     = (const float*)d_in[1];
    const float* W_init = (const float*)d_in[2];
    const float* b_init = (const float*)d_in[3];
    const float* W_edge = (const float*)d_in[4];
    const float* b_edge = (const float*)d_in[5];
    const float* Wi_gru = (const float*)d_in[6];
    const float* Wh_gru = (const float*)d_in[7];
    const float* bi_gru = (const float*)d_in[8];
    const float* bh_gru = (const float*)d_in[9];
    const float* W_ri   = (const float*)d_in[10];
    const float* b_ri   = (const float*)d_in[11];
    const float* W_rj   = (const float*)d_in[12];
    const float* b_rj   = (const float*)d_in[13];
    const int*   recv   = (const int*)d_in[14];
    const int*   send   = (const int*)d_in[15];
    float* out = (float*)d_out;

    init_kernel<<<NPAD / 16, 256>>>(nf, W_init, b_init);

    for (int it = 0; it < MPITERS; it++) {
        t_kernel<<<(NN + 63) / 64, 256>>>(W_edge, b_edge);
        zero_msg_kernel<<<(NPAD * MM + 255) / 256, 256>>>();
        edge_kernel<<<EE / 16, 256>>>(ef, recv, send);
        gru_kernel<<<NPAD / 16, 256>>>(Wi_gru, Wh_gru, bi_gru, bh_gru);
    }

    zero_out_kernel<<<1, 1>>>(out);
    readout_kernel<<<(NN + 255) / 256, 256>>>(W_ri, b_ri, W_rj, b_rj, out);
}